// round 14
// baseline (speedup 1.0000x reference)
#include <cuda_runtime.h>
#include <cuda_bf16.h>
#include <math.h>

#define NSEQ 80
#define SW 256
#define C 128
#define NH 8
#define DH 16
#define FF 512
#define NTOK (NSEQ*SW)          // 20480
#define TOKC (NTOK*C)           // 2621440

#define OUT_L 0
#define OUT_R TOKC
#define RAW_L (2*TOKC)
#define RAW_R (2*TOKC + NSEQ*SW*SW*NH)

// Scratch (device globals: allocation-free)
__device__ float g_k[2][TOKC];
__device__ float g_q[2][TOKC];
__device__ float g_v[2][TOKC];
__device__ float g_msg[2][TOKC];
__device__ float g_w1f[16*32*32*4];   // W1 tf32 frag layout
__device__ float g_w2f[64*8*32*4];    // W2 tf32 frag layout

// ---- mma / async helpers ----
__device__ __forceinline__ unsigned f2tf32(float x) {
    unsigned r; asm("cvt.rna.tf32.f32 %0, %1;" : "=r"(r) : "f"(x)); return r;
}
__device__ __forceinline__ void mma_tf32(float* c,
    unsigned a0, unsigned a1, unsigned a2, unsigned a3,
    unsigned b0, unsigned b1)
{
    asm("mma.sync.aligned.m16n8k8.row.col.f32.tf32.tf32.f32 "
        "{%0,%1,%2,%3},{%4,%5,%6,%7},{%8,%9},{%0,%1,%2,%3};"
        : "+f"(c[0]), "+f"(c[1]), "+f"(c[2]), "+f"(c[3])
        : "r"(a0), "r"(a1), "r"(a2), "r"(a3), "r"(b0), "r"(b1));
}
__device__ __forceinline__ void mma_bf16(float* c,
    const unsigned* a, unsigned b0, unsigned b1)
{
    asm("mma.sync.aligned.m16n8k16.row.col.f32.bf16.bf16.f32 "
        "{%0,%1,%2,%3},{%4,%5,%6,%7},{%8,%9},{%0,%1,%2,%3};"
        : "+f"(c[0]), "+f"(c[1]), "+f"(c[2]), "+f"(c[3])
        : "r"(a[0]), "r"(a[1]), "r"(a[2]), "r"(a[3]), "r"(b0), "r"(b1));
}
__device__ __forceinline__ void bfsplit(float2 v, unsigned& hi, unsigned& lo) {
    __nv_bfloat162 h = __floats2bfloat162_rn(v.x, v.y);
    float2 hf = __bfloat1622float2(h);
    __nv_bfloat162 l = __floats2bfloat162_rn(v.x - hf.x, v.y - hf.y);
    hi = *reinterpret_cast<unsigned*>(&h);
    lo = *reinterpret_cast<unsigned*>(&l);
}
__device__ __forceinline__ void cpasync16(unsigned sdst, const void* gsrc) {
    asm volatile("cp.async.cg.shared.global [%0], [%1], 16;" :: "r"(sdst), "l"(gsrc));
}
__device__ __forceinline__ void ldsm_x4(unsigned* r, unsigned saddr) {
    asm volatile("ldmatrix.sync.aligned.m8n8.x4.shared.b16 {%0,%1,%2,%3}, [%4];"
        : "=r"(r[0]), "=r"(r[1]), "=r"(r[2]), "=r"(r[3]) : "r"(saddr));
}

// ---------------------------------------------------------------------------
// Kernel 0: W1/W2 -> tf32 fragment layouts.
// ---------------------------------------------------------------------------
__global__ __launch_bounds__(256) void prep_kernel(
    const float* __restrict__ w1, const float* __restrict__ w2)
{
    int i = blockIdx.x * 256 + threadIdx.x;     // 0..32767
    if (i < 16384) {
        int lane = i & 31, tp = (i >> 5) & 31, ks = i >> 10;
        int gid = lane >> 2, tig = lane & 3;
        int k0 = ks*8, n0 = (2*tp)*8, n1 = (2*tp+1)*8;
        float4 o;
        o.x = __uint_as_float(f2tf32(w1[(k0+tig)*FF   + n0+gid]));
        o.y = __uint_as_float(f2tf32(w1[(k0+tig+4)*FF + n0+gid]));
        o.z = __uint_as_float(f2tf32(w1[(k0+tig)*FF   + n1+gid]));
        o.w = __uint_as_float(f2tf32(w1[(k0+tig+4)*FF + n1+gid]));
        ((float4*)g_w1f)[i] = o;
    } else {
        int j = i - 16384;
        int lane = j & 31, tp = (j >> 5) & 7, ks = j >> 8;
        int gid = lane >> 2, tig = lane & 3;
        int k0 = ks*8, n0 = (2*tp)*8, n1 = (2*tp+1)*8;
        float4 o;
        o.x = __uint_as_float(f2tf32(w2[(k0+tig)*C   + n0+gid]));
        o.y = __uint_as_float(f2tf32(w2[(k0+tig+4)*C + n0+gid]));
        o.z = __uint_as_float(f2tf32(w2[(k0+tig)*C   + n1+gid]));
        o.w = __uint_as_float(f2tf32(w2[(k0+tig+4)*C + n1+gid]));
        ((float4*)g_w2f)[j] = o;
    }
}

// ---------------------------------------------------------------------------
// Kernel 1: per-head KQV projection with coalesced smem-staged stores.
// ---------------------------------------------------------------------------
__global__ __launch_bounds__(256) void proj_kernel(
    const float* __restrict__ feat_l, const float* __restrict__ feat_r,
    const float* __restrict__ kqv_w)
{
    __shared__ float sW[16*48];
    __shared__ float sO[8*548];
    int tid = threadIdx.x;
    for (int i = tid; i < 16*48; i += 256) sW[i] = kqv_w[i];

    int side = blockIdx.y;
    const float* feat = side ? feat_r : feat_l;
    int rl = tid >> 3;
    int h  = tid & 7;
    int row = blockIdx.x * 32 + rl;
    __syncthreads();

    float x[16];
    const float4* xp = (const float4*)(feat + (long)row*C + h*DH);
#pragma unroll
    for (int i = 0; i < 4; i++) {
        float4 t = xp[i];
        x[4*i+0]=t.x; x[4*i+1]=t.y; x[4*i+2]=t.z; x[4*i+3]=t.w;
    }
    float o[48];
#pragma unroll
    for (int j = 0; j < 48; j++) o[j] = 0.f;
#pragma unroll
    for (int i = 0; i < 16; i++) {
        float xi = x[i];
#pragma unroll
        for (int j = 0; j < 48; j++) o[j] = fmaf(xi, sW[i*48+j], o[j]);
    }

    int nn = row >> 8;
    int s0 = (blockIdx.x * 32) & 255;
    float* gdst[3] = { g_k[side], g_q[side], g_v[side] };

#pragma unroll
    for (int a = 0; a < 3; a++) {
        __syncthreads();
#pragma unroll
        for (int d = 0; d < 16; d++) sO[h*548 + rl*17 + d] = o[a*16 + d];
        __syncthreads();
        float* gp = gdst[a] + (((long)(nn*NH))*SW + s0) * DH;
        for (int j = tid; j < 4096; j += 256) {
            int hh = j >> 9, rem = j & 511, ss = rem >> 4, d = rem & 15;
            gp[(long)hh*SW*DH + ss*DH + d] = sO[hh*548 + ss*17 + d];
        }
    }
}

// ---------------------------------------------------------------------------
// Kernel 2: cross attention. QK: bf16 2-split m16n8k16. AV: tf32 k8.
// prev double-buffered via cp.async (overlaps DRAM stream with compute).
// sP layout [l][s*8+h] pitch 260 (16B-aligned float4 stage/writeback).
// ---------------------------------------------------------------------------
#define PL2 260   // sP pitch per l
#define PK 172    // sK pitch per s:  s*172 + h*20 + d
#define PV 168    // sV pitch per s
#define ATTN_SMEM ((2*32*PL2 + 32*PK + 32*PV)*4)   // 110080 B

__global__ __launch_bounds__(256, 2) void attn_kernel(
    const float* __restrict__ prev_l, const float* __restrict__ prev_r,
    float* __restrict__ d_out)
{
    extern __shared__ float sm[];
    float* sPA = sm;                      // 32*260
    float* sPB = sm + 32*PL2;             // 32*260
    float* sK  = sm + 2*32*PL2;           // 32*172
    float* sV  = sm + 2*32*PL2 + 32*PK;   // 32*168

    int tid = threadIdx.x;
    int lane = tid & 31;
    int h = tid >> 5;                // warp = head
    int gid = lane >> 2, tig = lane & 3;
    int lt = blockIdx.x, nn = blockIdx.y, side = blockIdx.z;
    int l0 = lt * 32;

    const float* prev = side ? prev_r : prev_l;
    float* raw = d_out + (side ? RAW_R : RAW_L);
    const float* qb = g_q[side];
    const float* kb = g_k[side ^ 1];
    const float* vb = g_v[side ^ 1];

    // decompose tid once for staging loops
    int sl = tid >> 3;               // l for prev staging (per i-offset)
    // prev staging mapping: idx = i*256+tid -> l=idx>>6, rem=idx&63, s=rem>>1, hb=(rem&1)*4
    unsigned sPAs = (unsigned)__cvta_generic_to_shared(sPA);
    unsigned sPBs = (unsigned)__cvta_generic_to_shared(sPB);

    // ---- Q a-frags (k16 over full DH)
    unsigned qhi[2][4], qlo[2][4];
    {
        const float* qbase = qb + (((long)(nn*NH + h))*SW + l0)*DH;
#pragma unroll
        for (int mt = 0; mt < 2; mt++) {
            const float* r0 = qbase + (mt*16 + gid)*DH;
            const float* r1 = r0 + 8*DH;
            bfsplit(*(const float2*)(r0 + 2*tig),     qhi[mt][0], qlo[mt][0]);
            bfsplit(*(const float2*)(r1 + 2*tig),     qhi[mt][1], qlo[mt][1]);
            bfsplit(*(const float2*)(r0 + 2*tig + 8), qhi[mt][2], qlo[mt][2]);
            bfsplit(*(const float2*)(r1 + 2*tig + 8), qhi[mt][3], qlo[mt][3]);
        }
    }

    float z00 = 0.f, z01 = 0.f, z10 = 0.f, z11 = 0.f;
    float acc[2][2][4];
#pragma unroll
    for (int mt = 0; mt < 2; mt++)
#pragma unroll
        for (int nt = 0; nt < 2; nt++)
#pragma unroll
            for (int j = 0; j < 4; j++) acc[mt][nt][j] = 0.f;

    long pvbase = ((long)(nn*SW + l0))*SW*NH;   // + l*SW*NH + s*NH + hb

    // ---- preloop: stage K/V[0] (plain), issue prev[0] cp.async
    {
#pragma unroll
        for (int i = 0; i < 4; i++) {
            int f = i*256 + tid;
            int hh = f >> 7, rem = f & 127;
            int s = rem >> 2, dq = rem & 3;
            long src = (((long)(nn*NH + hh))*SW + s)*DH + dq*4;
            *(float4*)(sK + s*PK + hh*20 + dq*4) = *(const float4*)(kb + src);
            *(float4*)(sV + s*PV + hh*20 + dq*4) = *(const float4*)(vb + src);
        }
#pragma unroll
        for (int i = 0; i < 8; i++) {
            int f = i*256 + tid;
            int l = f >> 6, rem = f & 63;
            int s = rem >> 1, hb = (rem & 1) * 4;
            cpasync16(sPAs + (unsigned)((l*PL2 + s*8 + hb)*4),
                      prev + pvbase + (long)l*SW*NH + s*NH + hb);
        }
        asm volatile("cp.async.commit_group;");
    }

    for (int ch = 0; ch < 8; ch++) {
        int s0 = ch * 32;
        float* sPc = (ch & 1) ? sPB : sPA;
        unsigned sPo = (ch & 1) ? sPAs : sPBs;

        asm volatile("cp.async.wait_group 0;");
        __syncthreads();   // prev[ch] + K/V[ch] staged; writeback(ch-1) done

        // ---- issue prev[ch+1] into the other buffer (overlaps compute)
        if (ch < 7) {
#pragma unroll
            for (int i = 0; i < 8; i++) {
                int f = i*256 + tid;
                int l = f >> 6, rem = f & 63;
                int s = rem >> 1, hb = (rem & 1) * 4;
                cpasync16(sPo + (unsigned)((l*PL2 + s*8 + hb)*4),
                          prev + pvbase + (long)l*SW*NH + (s0+32+s)*NH + hb);
            }
            asm volatile("cp.async.commit_group;");
        }

        // ---- QK mma (bf16 split, k16)
        float c[2][4][4];
#pragma unroll
        for (int mt = 0; mt < 2; mt++)
#pragma unroll
            for (int st = 0; st < 4; st++)
#pragma unroll
                for (int j = 0; j < 4; j++) c[mt][st][j] = 0.f;

#pragma unroll
        for (int st = 0; st < 4; st++) {
            const float* kr = sK + (st*8 + gid)*PK + h*20;
            unsigned k0h, k0l, k1h, k1l;
            bfsplit(*(const float2*)(kr + 2*tig),     k0h, k0l);
            bfsplit(*(const float2*)(kr + 2*tig + 8), k1h, k1l);
#pragma unroll
            for (int mt = 0; mt < 2; mt++) {
                mma_bf16(c[mt][st], qhi[mt], k0h, k1h);
                mma_bf16(c[mt][st], qhi[mt], k0l, k1l);
                mma_bf16(c[mt][st], qlo[mt], k0h, k1h);
            }
        }

        // ---- prev add (from sPc), raw back into sPc, exp, z
#pragma unroll
        for (int mt = 0; mt < 2; mt++) {
#pragma unroll
            for (int st = 0; st < 4; st++) {
                float* pp = sPc + (mt*16 + gid)*PL2 + (st*8 + 2*tig)*8 + h;
                float r0 = c[mt][st][0] + pp[0];
                float r1 = c[mt][st][1] + pp[8];
                float r2 = c[mt][st][2] + pp[8*PL2];
                float r3 = c[mt][st][3] + pp[8*PL2 + 8];
                pp[0] = r0; pp[8] = r1; pp[8*PL2] = r2; pp[8*PL2 + 8] = r3;
                float e0 = __expf(0.25f*r0), e1 = __expf(0.25f*r1);
                float e2 = __expf(0.25f*r2), e3 = __expf(0.25f*r3);
                if (mt == 0) { z00 += e0 + e1; z01 += e2 + e3; }
                else         { z10 += e0 + e1; z11 += e2 + e3; }
                c[mt][st][0] = e0; c[mt][st][1] = e1; c[mt][st][2] = e2; c[mt][st][3] = e3;
            }
        }

        // ---- AV mma (tf32 k8)
        int srcA = (lane & 28) | (tig >> 1);
        int srcB = srcA + 2;
        bool odd = (tig & 1);
#pragma unroll
        for (int st = 0; st < 4; st++) {
            unsigned a[2][4];
#pragma unroll
            for (int mt = 0; mt < 2; mt++) {
                float e0 = c[mt][st][0], e1 = c[mt][st][1];
                float e2 = c[mt][st][2], e3 = c[mt][st][3];
                float g00 = __shfl_sync(0xffffffffu, e0, srcA);
                float g01 = __shfl_sync(0xffffffffu, e1, srcA);
                float g20 = __shfl_sync(0xffffffffu, e2, srcA);
                float g21 = __shfl_sync(0xffffffffu, e3, srcA);
                float h00 = __shfl_sync(0xffffffffu, e0, srcB);
                float h01 = __shfl_sync(0xffffffffu, e1, srcB);
                float h20 = __shfl_sync(0xffffffffu, e2, srcB);
                float h21 = __shfl_sync(0xffffffffu, e3, srcB);
                a[mt][0] = f2tf32(odd ? g01 : g00);
                a[mt][1] = f2tf32(odd ? g21 : g20);
                a[mt][2] = f2tf32(odd ? h01 : h00);
                a[mt][3] = f2tf32(odd ? h21 : h20);
            }
            const float* vr0 = sV + (st*8 + tig)*PV + h*20;
            const float* vr1 = sV + (st*8 + tig + 4)*PV + h*20;
#pragma unroll
            for (int nt = 0; nt < 2; nt++) {
                unsigned vb0 = f2tf32(vr0[nt*8 + gid]);
                unsigned vb1 = f2tf32(vr1[nt*8 + gid]);
                mma_tf32(acc[0][nt], a[0][0], a[0][1], a[0][2], a[0][3], vb0, vb1);
                mma_tf32(acc[1][nt], a[1][0], a[1][1], a[1][2], a[1][3], vb0, vb1);
            }
        }

        __syncthreads();   // compute(ch) done everywhere

        // ---- raw writeback from sPc (coalesced float4)
#pragma unroll
        for (int i = 0; i < 8; i++) {
            int f = i*256 + tid;
            int l = f >> 6, rem = f & 63;
            int s = rem >> 1, hb = (rem & 1) * 4;
            float4 rv = *(float4*)(sPc + l*PL2 + s*8 + hb);
            *(float4*)(raw + pvbase + (long)l*SW*NH + (s0+s)*NH + hb) = rv;
        }
        // ---- stage K/V[ch+1] (plain)
        if (ch < 7) {
#pragma unroll
            for (int i = 0; i < 4; i++) {
                int f = i*256 + tid;
                int hh = f >> 7, rem = f & 127;
                int s = rem >> 2, dq = rem & 3;
                long src = (((long)(nn*NH + hh))*SW + s0+32 + s)*DH + dq*4;
                *(float4*)(sK + s*PK + hh*20 + dq*4) = *(const float4*)(kb + src);
                *(float4*)(sV + s*PV + hh*20 + dq*4) = *(const float4*)(vb + src);
            }
        }
    }

    // ---- z quad-reduce
    z00 += __shfl_xor_sync(0xffffffffu, z00, 1); z00 += __shfl_xor_sync(0xffffffffu, z00, 2);
    z01 += __shfl_xor_sync(0xffffffffu, z01, 1); z01 += __shfl_xor_sync(0xffffffffu, z01, 2);
    z10 += __shfl_xor_sync(0xffffffffu, z10, 1); z10 += __shfl_xor_sync(0xffffffffu, z10, 2);
    z11 += __shfl_xor_sync(0xffffffffu, z11, 1); z11 += __shfl_xor_sync(0xffffffffu, z11, 2);
    float iz[2][2] = { {1.f/z00, 1.f/z01}, {1.f/z10, 1.f/z11} };

    // ---- msg out
    float* mb = g_msg[side];
#pragma unroll
    for (int mt = 0; mt < 2; mt++) {
#pragma unroll
        for (int nt = 0; nt < 2; nt++) {
            long base = ((long)(nn*SW + l0 + mt*16 + gid))*C + h*DH + nt*8 + 2*tig;
            *(float2*)(mb + base)       = make_float2(acc[mt][nt][0]*iz[mt][0], acc[mt][nt][1]*iz[mt][0]);
            *(float2*)(mb + base + 8*C) = make_float2(acc[mt][nt][2]*iz[mt][1], acc[mt][nt][3]*iz[mt][1]);
        }
    }
}

// ---------------------------------------------------------------------------
// Kernel 3: fused LN1 + FFN (tf32 mma) + residual + LN2.
// 64 rows/block, 512 threads: halves per-block W traffic; ldmatrix a-frags.
// ---------------------------------------------------------------------------
#define XPITCH 132
#define HPITCH 516
#define FFN_SMEM ((64*XPITCH + 64*HPITCH)*4)   // 165888 B

__global__ __launch_bounds__(512, 1) void ffn_kernel(
    const float* __restrict__ feat_l, const float* __restrict__ feat_r,
    const float* __restrict__ b1, const float* __restrict__ b2,
    const float* __restrict__ lg1, const float* __restrict__ lb1,
    const float* __restrict__ lg2, const float* __restrict__ lb2,
    float* __restrict__ d_out)
{
    extern __shared__ float smem[];
    float* sX = smem;                 // 64 x 132
    float* sH = smem + 64*XPITCH;     // 64 x 516
    int tid  = threadIdx.x;
    int side = blockIdx.y;
    const float* feat = side ? feat_r : feat_l;
    const float* msg  = g_msg[side];
    float* outp = d_out + (side ? OUT_R : OUT_L);
    int row0 = blockIdx.x * 64;
    int w = tid >> 5, lane = tid & 31;
    int gid = lane >> 2, tig = lane & 3;
    // ldmatrix lane mapping: tiles {rows 0-7 k0, rows 8-15 k0, rows 0-7 k0+4, rows 8-15 k0+4}
    int row_off = ((lane >> 3) & 1)*8 + (lane & 7);
    int khB = (lane >> 4) * 16;

    for (int j = tid; j < 2048; j += 512) {
        int r = j >> 5, c4 = j & 31;
        long gi = ((long)(row0+r))*C + c4*4;
        float4 a = *(const float4*)(feat + gi);
        float4 b = *(const float4*)(msg + gi);
        a.x += b.x; a.y += b.y; a.z += b.z; a.w += b.w;
        *(float4*)(&sX[r*XPITCH + c4*4]) = a;
    }
    __syncthreads();

    // LN1: 16 warps x 4 rows = 64
#pragma unroll
    for (int rr = 0; rr < 4; rr++) {
        int r = w*4 + rr;
        float v0 = sX[r*XPITCH+lane],    v1 = sX[r*XPITCH+lane+32];
        float v2 = sX[r*XPITCH+lane+64], v3 = sX[r*XPITCH+lane+96];
        float sum = v0+v1+v2+v3;
        float sq  = v0*v0+v1*v1+v2*v2+v3*v3;
        for (int o = 16; o; o >>= 1) {
            sum += __shfl_xor_sync(~0u, sum, o);
            sq  += __shfl_xor_sync(~0u, sq,  o);
        }
        float mu = sum*(1.f/128.f);
        float rs = rsqrtf(sq*(1.f/128.f) - mu*mu + 1e-5f);
        sX[r*XPITCH+lane]    = (v0-mu)*rs*lg1[lane]    + lb1[lane];
        sX[r*XPITCH+lane+32] = (v1-mu)*rs*lg1[lane+32] + lb1[lane+32];
        sX[r*XPITCH+lane+64] = (v2-mu)*rs*lg1[lane+64] + lb1[lane+64];
        sX[r*XPITCH+lane+96] = (v3-mu)*rs*lg1[lane+96] + lb1[lane+96];
    }
    __syncthreads();

    unsigned sXs = (unsigned)__cvta_generic_to_shared(sX);
    unsigned sHs = (unsigned)__cvta_generic_to_shared(sH);
    unsigned aBase1 = sXs + (unsigned)(row_off*XPITCH*4 + khB);
    unsigned aBase2 = sHs + (unsigned)(row_off*HPITCH*4 + khB);

    // GEMM1: warp = unique cols [w*32,+32) x all 64 rows (4 m16 tiles)
    {
        float acc[4][4][4];
#pragma unroll
        for (int mt = 0; mt < 4; mt++)
#pragma unroll
            for (int t = 0; t < 4; t++)
#pragma unroll
                for (int j = 0; j < 4; j++) acc[mt][t][j] = 0.f;

#pragma unroll 2
        for (int ks = 0; ks < 16; ks++) {
            unsigned a[4][4];
#pragma unroll
            for (int mt = 0; mt < 4; mt++) {
                unsigned rr[4];
                ldsm_x4(rr, aBase1 + (unsigned)(mt*16*XPITCH*4 + ks*32));
                a[mt][0] = f2tf32(__uint_as_float(rr[0]));
                a[mt][1] = f2tf32(__uint_as_float(rr[1]));
                a[mt][2] = f2tf32(__uint_as_float(rr[2]));
                a[mt][3] = f2tf32(__uint_as_float(rr[3]));
            }
            const float4* bp = (const float4*)g_w1f + (ks*32 + w*2)*32 + lane;
            float4 b0 = bp[0], b1v = bp[32];
#pragma unroll
            for (int mt = 0; mt < 4; mt++) {
                mma_tf32(acc[mt][0], a[mt][0],a[mt][1],a[mt][2],a[mt][3], __float_as_uint(b0.x),  __float_as_uint(b0.y));
                mma_tf32(acc[mt][1], a[mt][0],a[mt][1],a[mt][2],a[mt][3], __float_as_uint(b0.z),  __float_as_uint(b0.w));
                mma_tf32(acc[mt][2], a[mt][0],a[mt][1],a[mt][2],a[mt][3], __float_as_uint(b1v.x), __float_as_uint(b1v.y));
                mma_tf32(acc[mt][3], a[mt][0],a[mt][1],a[mt][2],a[mt][3], __float_as_uint(b1v.z), __float_as_uint(b1v.w));
            }
        }
#pragma unroll
        for (int mt = 0; mt < 4; mt++) {
#pragma unroll
            for (int t = 0; t < 4; t++) {
                int col = w*32 + t*8 + 2*tig;
                int r0 = mt*16 + gid, r1 = r0 + 8;
                float h00 = acc[mt][t][0] + b1[col];
                float h01 = acc[mt][t][1] + b1[col+1];
                float h10 = acc[mt][t][2] + b1[col];
                float h11 = acc[mt][t][3] + b1[col+1];
                h00 = 0.5f*h00*(1.f + erff(h00*0.70710678118654752f));
                h01 = 0.5f*h01*(1.f + erff(h01*0.70710678118654752f));
                h10 = 0.5f*h10*(1.f + erff(h10*0.70710678118654752f));
                h11 = 0.5f*h11*(1.f + erff(h11*0.70710678118654752f));
                *(float2*)(&sH[r0*HPITCH + col]) =
                    make_float2(__uint_as_float(f2tf32(h00)), __uint_as_float(f2tf32(h01)));
                *(float2*)(&sH[r1*HPITCH + col]) =
                    make_float2(__uint_as_float(f2tf32(h10)), __uint_as_float(f2tf32(h11)));
            }
        }
    }
    __syncthreads();

    // GEMM2: warp = unique cols [w*8,+8) x all 64 rows
    float acc2[4][4];
#pragma unroll
    for (int mt = 0; mt < 4; mt++)
#pragma unroll
        for (int j = 0; j < 4; j++) acc2[mt][j] = 0.f;
    {
        const float* w2p = g_w2f + ((w >> 1)*32 + lane)*4 + (w & 1)*2;
#pragma unroll 4
        for (int ks = 0; ks < 64; ks++) {
            float2 b = *(const float2*)(w2p + ks*8*32*4);
#pragma unroll
            for (int mt = 0; mt < 4; mt++) {
                unsigned a[4];
                ldsm_x4(a, aBase2 + (unsigned)(mt*16*HPITCH*4 + ks*32));
                mma_tf32(acc2[mt], a[0],a[1],a[2],a[3], __float_as_uint(b.x), __float_as_uint(b.y));
            }
        }
    }
    __syncthreads();   // reads of sH done; reuse as out tile

#pragma unroll
    for (int mt = 0; mt < 4; mt++) {
        int col = w*8 + 2*tig;
        int r0 = mt*16 + gid, r1 = r0 + 8;
        float2 lo, hi;
        lo.x = acc2[mt][0] + b2[col]   + sX[r0*XPITCH + col];
        lo.y = acc2[mt][1] + b2[col+1] + sX[r0*XPITCH + col + 1];
        hi.x = acc2[mt][2] + b2[col]   + sX[r1*XPITCH + col];
        hi.y = acc2[mt][3] + b2[col+1] + sX[r1*XPITCH + col + 1];
        *(float2*)(&sH[r0*XPITCH + col]) = lo;
        *(float2*)(&sH[r1*XPITCH + col]) = hi;
    }
    __syncthreads();

    // LN2 + write out
#pragma unroll
    for (int rr = 0; rr < 4; rr++) {
        int r = w*4 + rr;
        float v0 = sH[r*XPITCH+lane],    v1 = sH[r*XPITCH+lane+32];
        float v2 = sH[r*XPITCH+lane+64], v3 = sH[r*XPITCH+lane+96];
        float sum = v0+v1+v2+v3;
        float sq  = v0*v0+v1*v1+v2*v2+v3*v3;
        for (int o = 16; o; o >>= 1) {
            sum += __shfl_xor_sync(~0u, sum, o);
            sq  += __shfl_xor_sync(~0u, sq,  o);
        }
        float mu = sum*(1.f/128.f);
        float rs = rsqrtf(sq*(1.f/128.f) - mu*mu + 1e-5f);
        long go = ((long)(row0+r))*C;
        outp[go+lane]    = (v0-mu)*rs*lg2[lane]    + lb2[lane];
        outp[go+lane+32] = (v1-mu)*rs*lg2[lane+32] + lb2[lane+32];
        outp[go+lane+64] = (v2-mu)*rs*lg2[lane+64] + lb2[lane+64];
        outp[go+lane+96] = (v3-mu)*rs*lg2[lane+96] + lb2[lane+96];
    }
}

// ---------------------------------------------------------------------------
extern "C" void kernel_launch(void* const* d_in, const int* in_sizes, int n_in,
                              void* d_out, int out_size)
{
    const float* feat_l = (const float*)d_in[0];
    const float* feat_r = (const float*)d_in[1];
    const float* prev_l = (const float*)d_in[2];
    const float* prev_r = (const float*)d_in[3];
    const float* kqv_w  = (const float*)d_in[4];
    const float* ff_w1  = (const float*)d_in[5];
    const float* ff_b1  = (const float*)d_in[6];
    const float* ff_w2  = (const float*)d_in[7];
    const float* ff_b2  = (const float*)d_in[8];
    const float* ln1_g  = (const float*)d_in[9];
    const float* ln1_b  = (const float*)d_in[10];
    const float* ln2_g  = (const float*)d_in[11];
    const float* ln2_b  = (const float*)d_in[12];
    float* out = (float*)d_out;

    cudaFuncSetAttribute(ffn_kernel, cudaFuncAttributeMaxDynamicSharedMemorySize, FFN_SMEM);
    cudaFuncSetAttribute(attn_kernel, cudaFuncAttributeMaxDynamicSharedMemorySize, ATTN_SMEM);

    prep_kernel<<<128, 256>>>(ff_w1, ff_w2);
    proj_kernel<<<dim3(NTOK/32, 2), 256>>>(feat_l, feat_r, kqv_w);
    attn_kernel<<<dim3(SW/32, NSEQ, 2), 256, ATTN_SMEM>>>(prev_l, prev_r, out);
    ffn_kernel<<<dim3(NTOK/64, 2), 512, FFN_SMEM>>>(
        feat_l, feat_r, ff_b1, ff_b2,
        ln1_g, ln1_b, ln2_g, ln2_b, out);
}

// round 15
// speedup vs baseline: 1.1608x; 1.1608x over previous
#include <cuda_runtime.h>
#include <cuda_bf16.h>
#include <math.h>

#define NSEQ 80
#define SW 256
#define C 128
#define NH 8
#define DH 16
#define FF 512
#define NTOK (NSEQ*SW)          // 20480
#define TOKC (NTOK*C)           // 2621440

#define OUT_L 0
#define OUT_R TOKC
#define RAW_L (2*TOKC)
#define RAW_R (2*TOKC + NSEQ*SW*SW*NH)

// Scratch (device globals: allocation-free)
__device__ float g_k[2][TOKC];
__device__ float g_q[2][TOKC];
__device__ float g_v[2][TOKC];
__device__ float g_msg[2][TOKC];
__device__ float g_w1f[16*32*32*4];   // W1 tf32 frag layout
__device__ float g_w2f[64*8*32*4];    // W2 tf32 frag layout

// ---- mma helpers ----
__device__ __forceinline__ unsigned f2tf32(float x) {
    unsigned r; asm("cvt.rna.tf32.f32 %0, %1;" : "=r"(r) : "f"(x)); return r;
}
__device__ __forceinline__ void mma_tf32(float* c,
    unsigned a0, unsigned a1, unsigned a2, unsigned a3,
    unsigned b0, unsigned b1)
{
    asm("mma.sync.aligned.m16n8k8.row.col.f32.tf32.tf32.f32 "
        "{%0,%1,%2,%3},{%4,%5,%6,%7},{%8,%9},{%0,%1,%2,%3};"
        : "+f"(c[0]), "+f"(c[1]), "+f"(c[2]), "+f"(c[3])
        : "r"(a0), "r"(a1), "r"(a2), "r"(a3), "r"(b0), "r"(b1));
}
__device__ __forceinline__ void mma_bf16(float* c,
    const unsigned* a, unsigned b0, unsigned b1)
{
    asm("mma.sync.aligned.m16n8k16.row.col.f32.bf16.bf16.f32 "
        "{%0,%1,%2,%3},{%4,%5,%6,%7},{%8,%9},{%0,%1,%2,%3};"
        : "+f"(c[0]), "+f"(c[1]), "+f"(c[2]), "+f"(c[3])
        : "r"(a[0]), "r"(a[1]), "r"(a[2]), "r"(a[3]), "r"(b0), "r"(b1));
}
__device__ __forceinline__ void bfsplit(float2 v, unsigned& hi, unsigned& lo) {
    __nv_bfloat162 h = __floats2bfloat162_rn(v.x, v.y);
    float2 hf = __bfloat1622float2(h);
    __nv_bfloat162 l = __floats2bfloat162_rn(v.x - hf.x, v.y - hf.y);
    hi = *reinterpret_cast<unsigned*>(&h);
    lo = *reinterpret_cast<unsigned*>(&l);
}
__device__ __forceinline__ void ldsm_x4(unsigned* r, unsigned saddr) {
    asm volatile("ldmatrix.sync.aligned.m8n8.x4.shared.b16 {%0,%1,%2,%3}, [%4];"
        : "=r"(r[0]), "=r"(r[1]), "=r"(r[2]), "=r"(r[3]) : "r"(saddr));
}

// ---------------------------------------------------------------------------
// Kernel 1: per-head KQV projection (+ W1/W2 frag prep folded into first
// 128 blocks of side 0).
// ---------------------------------------------------------------------------
__global__ __launch_bounds__(256) void proj_kernel(
    const float* __restrict__ feat_l, const float* __restrict__ feat_r,
    const float* __restrict__ kqv_w,
    const float* __restrict__ w1, const float* __restrict__ w2)
{
    __shared__ float sW[16*48];
    __shared__ float sO[8*548];
    int tid = threadIdx.x;
    for (int i = tid; i < 16*48; i += 256) sW[i] = kqv_w[i];

    int side = blockIdx.y;

    // ---- folded prep: W1/W2 -> tf32 fragment layouts
    if (side == 0 && blockIdx.x < 128) {
        int i = blockIdx.x * 256 + tid;     // 0..32767
        if (i < 16384) {
            int lane = i & 31, tp = (i >> 5) & 31, ks = i >> 10;
            int gid = lane >> 2, tig = lane & 3;
            int k0 = ks*8, n0 = (2*tp)*8, n1 = (2*tp+1)*8;
            float4 o;
            o.x = __uint_as_float(f2tf32(w1[(k0+tig)*FF   + n0+gid]));
            o.y = __uint_as_float(f2tf32(w1[(k0+tig+4)*FF + n0+gid]));
            o.z = __uint_as_float(f2tf32(w1[(k0+tig)*FF   + n1+gid]));
            o.w = __uint_as_float(f2tf32(w1[(k0+tig+4)*FF + n1+gid]));
            ((float4*)g_w1f)[i] = o;
        } else {
            int j = i - 16384;
            int lane = j & 31, tp = (j >> 5) & 7, ks = j >> 8;
            int gid = lane >> 2, tig = lane & 3;
            int k0 = ks*8, n0 = (2*tp)*8, n1 = (2*tp+1)*8;
            float4 o;
            o.x = __uint_as_float(f2tf32(w2[(k0+tig)*C   + n0+gid]));
            o.y = __uint_as_float(f2tf32(w2[(k0+tig+4)*C + n0+gid]));
            o.z = __uint_as_float(f2tf32(w2[(k0+tig)*C   + n1+gid]));
            o.w = __uint_as_float(f2tf32(w2[(k0+tig+4)*C + n1+gid]));
            ((float4*)g_w2f)[j] = o;
        }
    }

    const float* feat = side ? feat_r : feat_l;
    int rl = tid >> 3;
    int h  = tid & 7;
    int row = blockIdx.x * 32 + rl;
    __syncthreads();

    float x[16];
    const float4* xp = (const float4*)(feat + (long)row*C + h*DH);
#pragma unroll
    for (int i = 0; i < 4; i++) {
        float4 t = xp[i];
        x[4*i+0]=t.x; x[4*i+1]=t.y; x[4*i+2]=t.z; x[4*i+3]=t.w;
    }
    float o[48];
#pragma unroll
    for (int j = 0; j < 48; j++) o[j] = 0.f;
#pragma unroll
    for (int i = 0; i < 16; i++) {
        float xi = x[i];
#pragma unroll
        for (int j = 0; j < 48; j++) o[j] = fmaf(xi, sW[i*48+j], o[j]);
    }

    int nn = row >> 8;
    int s0 = (blockIdx.x * 32) & 255;
    float* gdst[3] = { g_k[side], g_q[side], g_v[side] };

#pragma unroll
    for (int a = 0; a < 3; a++) {
        __syncthreads();
#pragma unroll
        for (int d = 0; d < 16; d++) sO[h*548 + rl*17 + d] = o[a*16 + d];
        __syncthreads();
        float* gp = gdst[a] + (((long)(nn*NH))*SW + s0) * DH;
        for (int j = tid; j < 4096; j += 256) {
            int hh = j >> 9, rem = j & 511, ss = rem >> 4, d = rem & 15;
            gp[(long)hh*SW*DH + ss*DH + d] = sO[hh*548 + ss*17 + d];
        }
    }
}

// ---------------------------------------------------------------------------
// Kernel 2: cross attention. QK: bf16 2-split m16n8k16 (3 terms, fp32-grade).
// AV: tf32 k8. prev/raw staged via smem (conflict-free [l][h*33+s] layout);
// streaming cache hints on the prev/raw one-touch streams.
// ---------------------------------------------------------------------------
#define PL 268    // sP pitch per l:  l*268 + h*33 + s
#define PK 172    // sK pitch per s:  s*172 + h*20 + d
#define PV 168    // sV pitch per s
#define ATTN_SMEM ((32*PL + 32*PK + 32*PV)*4)   // 77824 B

__global__ __launch_bounds__(256, 2) void attn_kernel(
    const float* __restrict__ prev_l, const float* __restrict__ prev_r,
    float* __restrict__ d_out)
{
    extern __shared__ float sm[];
    float* sP = sm;                  // 32*268
    float* sK = sm + 32*PL;          // 32*172
    float* sV = sm + 32*PL + 32*PK;  // 32*168

    int tid = threadIdx.x;
    int lane = tid & 31;
    int h = tid >> 5;                // warp = head
    int gid = lane >> 2, tig = lane & 3;
    int lt = blockIdx.x, nn = blockIdx.y, side = blockIdx.z;
    int l0 = lt * 32;

    const float* prev = side ? prev_r : prev_l;
    float* raw = d_out + (side ? RAW_R : RAW_L);
    const float* qb = g_q[side];
    const float* kb = g_k[side ^ 1];
    const float* vb = g_v[side ^ 1];

    // ---- Q a-frags (k16 over full DH)
    unsigned qhi[2][4], qlo[2][4];
    {
        const float* qbase = qb + (((long)(nn*NH + h))*SW + l0)*DH;
#pragma unroll
        for (int mt = 0; mt < 2; mt++) {
            const float* r0 = qbase + (mt*16 + gid)*DH;
            const float* r1 = r0 + 8*DH;
            bfsplit(*(const float2*)(r0 + 2*tig),     qhi[mt][0], qlo[mt][0]);
            bfsplit(*(const float2*)(r1 + 2*tig),     qhi[mt][1], qlo[mt][1]);
            bfsplit(*(const float2*)(r0 + 2*tig + 8), qhi[mt][2], qlo[mt][2]);
            bfsplit(*(const float2*)(r1 + 2*tig + 8), qhi[mt][3], qlo[mt][3]);
        }
    }

    float z00 = 0.f, z01 = 0.f, z10 = 0.f, z11 = 0.f;
    float acc[2][2][4];
#pragma unroll
    for (int mt = 0; mt < 2; mt++)
#pragma unroll
        for (int nt = 0; nt < 2; nt++)
#pragma unroll
            for (int j = 0; j < 4; j++) acc[mt][nt][j] = 0.f;

    for (int ch = 0; ch < 8; ch++) {
        int s0 = ch * 32;
        __syncthreads();

        // ---- stage prev chunk [32l][32s][8h] -> sP[l][h][s]  (streaming read)
#pragma unroll
        for (int i = 0; i < 8; i++) {
            int f = i*256 + tid;
            int l = f >> 6, rem = f & 63;
            int s = rem >> 1, hb = (rem & 1) * 4;
            float4 pv = __ldcs((const float4*)(prev + (((long)(nn*SW + l0+l))*SW + s0+s)*NH + hb));
            float* dp = sP + l*PL + hb*33 + s;
            dp[0] = pv.x; dp[33] = pv.y; dp[66] = pv.z; dp[99] = pv.w;
        }
        // ---- stage K, V chunks
#pragma unroll
        for (int i = 0; i < 4; i++) {
            int f = i*256 + tid;
            int hh = f >> 7, rem = f & 127;
            int s = rem >> 2, dq = rem & 3;
            long src = (((long)(nn*NH + hh))*SW + s0 + s)*DH + dq*4;
            *(float4*)(sK + s*PK + hh*20 + dq*4) = *(const float4*)(kb + src);
            *(float4*)(sV + s*PV + hh*20 + dq*4) = *(const float4*)(vb + src);
        }
        __syncthreads();

        // ---- QK mma (bf16 split, k16): c[mt][st][4]
        float c[2][4][4];
#pragma unroll
        for (int mt = 0; mt < 2; mt++)
#pragma unroll
            for (int st = 0; st < 4; st++)
#pragma unroll
                for (int j = 0; j < 4; j++) c[mt][st][j] = 0.f;

#pragma unroll
        for (int st = 0; st < 4; st++) {
            const float* kr = sK + (st*8 + gid)*PK + h*20;
            unsigned k0h, k0l, k1h, k1l;
            bfsplit(*(const float2*)(kr + 2*tig),     k0h, k0l);
            bfsplit(*(const float2*)(kr + 2*tig + 8), k1h, k1l);
#pragma unroll
            for (int mt = 0; mt < 2; mt++) {
                mma_bf16(c[mt][st], qhi[mt], k0h, k1h);
                mma_bf16(c[mt][st], qhi[mt], k0l, k1l);
                mma_bf16(c[mt][st], qlo[mt], k0h, k1h);
            }
        }

        // ---- prev add, raw (in sP), exp, z
#pragma unroll
        for (int mt = 0; mt < 2; mt++) {
#pragma unroll
            for (int st = 0; st < 4; st++) {
                float* pp = sP + (mt*16 + gid)*PL + h*33 + st*8 + 2*tig;
                float r0 = c[mt][st][0] + pp[0];
                float r1 = c[mt][st][1] + pp[1];
                float r2 = c[mt][st][2] + pp[8*PL];
                float r3 = c[mt][st][3] + pp[8*PL + 1];
                pp[0] = r0; pp[1] = r1; pp[8*PL] = r2; pp[8*PL + 1] = r3;
                float e0 = __expf(0.25f*r0), e1 = __expf(0.25f*r1);
                float e2 = __expf(0.25f*r2), e3 = __expf(0.25f*r3);
                if (mt == 0) { z00 += e0 + e1; z01 += e2 + e3; }
                else         { z10 += e0 + e1; z11 += e2 + e3; }
                c[mt][st][0] = e0; c[mt][st][1] = e1; c[mt][st][2] = e2; c[mt][st][3] = e3;
            }
        }

        // ---- AV mma (tf32 k8)
        int srcA = (lane & 28) | (tig >> 1);
        int srcB = srcA + 2;
        bool odd = (tig & 1);
#pragma unroll
        for (int st = 0; st < 4; st++) {
            unsigned a[2][4];
#pragma unroll
            for (int mt = 0; mt < 2; mt++) {
                float e0 = c[mt][st][0], e1 = c[mt][st][1];
                float e2 = c[mt][st][2], e3 = c[mt][st][3];
                float g00 = __shfl_sync(0xffffffffu, e0, srcA);
                float g01 = __shfl_sync(0xffffffffu, e1, srcA);
                float g20 = __shfl_sync(0xffffffffu, e2, srcA);
                float g21 = __shfl_sync(0xffffffffu, e3, srcA);
                float h00 = __shfl_sync(0xffffffffu, e0, srcB);
                float h01 = __shfl_sync(0xffffffffu, e1, srcB);
                float h20 = __shfl_sync(0xffffffffu, e2, srcB);
                float h21 = __shfl_sync(0xffffffffu, e3, srcB);
                a[mt][0] = f2tf32(odd ? g01 : g00);
                a[mt][1] = f2tf32(odd ? g21 : g20);
                a[mt][2] = f2tf32(odd ? h01 : h00);
                a[mt][3] = f2tf32(odd ? h21 : h20);
            }
            const float* vr0 = sV + (st*8 + tig)*PV + h*20;
            const float* vr1 = sV + (st*8 + tig + 4)*PV + h*20;
#pragma unroll
            for (int nt = 0; nt < 2; nt++) {
                unsigned vb0 = f2tf32(vr0[nt*8 + gid]);
                unsigned vb1 = f2tf32(vr1[nt*8 + gid]);
                mma_tf32(acc[0][nt], a[0][0], a[0][1], a[0][2], a[0][3], vb0, vb1);
                mma_tf32(acc[1][nt], a[1][0], a[1][1], a[1][2], a[1][3], vb0, vb1);
            }
        }

        // ---- raw out: sP -> gmem (coalesced, streaming write)
        __syncthreads();
#pragma unroll
        for (int i = 0; i < 8; i++) {
            int f = i*256 + tid;
            int l = f >> 6, rem = f & 63;
            int s = rem >> 1, hb = (rem & 1) * 4;
            float* dp = sP + l*PL + hb*33 + s;
            float4 rv = make_float4(dp[0], dp[33], dp[66], dp[99]);
            __stcs((float4*)(raw + (((long)(nn*SW + l0+l))*SW + s0+s)*NH + hb), rv);
        }
    }

    // ---- z quad-reduce
    z00 += __shfl_xor_sync(0xffffffffu, z00, 1); z00 += __shfl_xor_sync(0xffffffffu, z00, 2);
    z01 += __shfl_xor_sync(0xffffffffu, z01, 1); z01 += __shfl_xor_sync(0xffffffffu, z01, 2);
    z10 += __shfl_xor_sync(0xffffffffu, z10, 1); z10 += __shfl_xor_sync(0xffffffffu, z10, 2);
    z11 += __shfl_xor_sync(0xffffffffu, z11, 1); z11 += __shfl_xor_sync(0xffffffffu, z11, 2);
    float iz[2][2] = { {1.f/z00, 1.f/z01}, {1.f/z10, 1.f/z11} };

    // ---- msg out
    float* mb = g_msg[side];
#pragma unroll
    for (int mt = 0; mt < 2; mt++) {
#pragma unroll
        for (int nt = 0; nt < 2; nt++) {
            long base = ((long)(nn*SW + l0 + mt*16 + gid))*C + h*DH + nt*8 + 2*tig;
            *(float2*)(mb + base)       = make_float2(acc[mt][nt][0]*iz[mt][0], acc[mt][nt][1]*iz[mt][0]);
            *(float2*)(mb + base + 8*C) = make_float2(acc[mt][nt][2]*iz[mt][1], acc[mt][nt][3]*iz[mt][1]);
        }
    }
}

// ---------------------------------------------------------------------------
// Kernel 3: fused LN1 + FFN (tf32 mma) + residual + LN2. 32 rows/block,
// 2 blocks/SM (r13 tiling), ldmatrix.x4 a-frags in both GEMMs.
// ---------------------------------------------------------------------------
#define XPITCH 132
#define HPITCH 516

__global__ __launch_bounds__(256, 2) void ffn_kernel(
    const float* __restrict__ feat_l, const float* __restrict__ feat_r,
    const float* __restrict__ b1, const float* __restrict__ b2,
    const float* __restrict__ lg1, const float* __restrict__ lb1,
    const float* __restrict__ lg2, const float* __restrict__ lb2,
    float* __restrict__ d_out)
{
    extern __shared__ float smem[];
    float* sX = smem;
    float* sH = smem + 32*XPITCH;
    int tid  = threadIdx.x;
    int side = blockIdx.y;
    const float* feat = side ? feat_r : feat_l;
    const float* msg  = g_msg[side];
    float* outp = d_out + (side ? OUT_R : OUT_L);
    int row0 = blockIdx.x * 32;
    int warp = tid >> 5, lane = tid & 31;
    int gid = lane >> 2, tig = lane & 3;
    // ldmatrix lane mapping: tiles {rows0-7 k0, rows8-15 k0, rows0-7 k+4, rows8-15 k+4}
    int row_off = ((lane >> 3) & 1)*8 + (lane & 7);
    int khB = (lane >> 4) * 16;

    for (int j = tid; j < 1024; j += 256) {
        int r = j >> 5, c4 = j & 31;
        long gi = ((long)(row0+r))*C + c4*4;
        float4 a = *(const float4*)(feat + gi);
        float4 b = *(const float4*)(msg + gi);
        a.x += b.x; a.y += b.y; a.z += b.z; a.w += b.w;
        *(float4*)(&sX[r*XPITCH + c4*4]) = a;
    }
    __syncthreads();

#pragma unroll
    for (int rr = 0; rr < 4; rr++) {
        int r = warp*4 + rr;
        float v0 = sX[r*XPITCH+lane],    v1 = sX[r*XPITCH+lane+32];
        float v2 = sX[r*XPITCH+lane+64], v3 = sX[r*XPITCH+lane+96];
        float sum = v0+v1+v2+v3;
        float sq  = v0*v0+v1*v1+v2*v2+v3*v3;
        for (int o = 16; o; o >>= 1) {
            sum += __shfl_xor_sync(~0u, sum, o);
            sq  += __shfl_xor_sync(~0u, sq,  o);
        }
        float mu = sum*(1.f/128.f);
        float rs = rsqrtf(sq*(1.f/128.f) - mu*mu + 1e-5f);
        sX[r*XPITCH+lane]    = (v0-mu)*rs*lg1[lane]    + lb1[lane];
        sX[r*XPITCH+lane+32] = (v1-mu)*rs*lg1[lane+32] + lb1[lane+32];
        sX[r*XPITCH+lane+64] = (v2-mu)*rs*lg1[lane+64] + lb1[lane+64];
        sX[r*XPITCH+lane+96] = (v3-mu)*rs*lg1[lane+96] + lb1[lane+96];
    }
    __syncthreads();

    unsigned sXs = (unsigned)__cvta_generic_to_shared(sX);
    unsigned sHs = (unsigned)__cvta_generic_to_shared(sH);
    unsigned aBase1 = sXs + (unsigned)(row_off*XPITCH*4 + khB);
    unsigned aBase2 = sHs + (unsigned)(row_off*HPITCH*4 + khB);

    // GEMM1: warp = cols [warp*64, +64) x rows 0..31 (2 m16 tiles)
    {
        float acc[2][8][4];
#pragma unroll
        for (int mt = 0; mt < 2; mt++)
#pragma unroll
            for (int t = 0; t < 8; t++)
#pragma unroll
                for (int j = 0; j < 4; j++) acc[mt][t][j] = 0.f;

#pragma unroll 2
        for (int ks = 0; ks < 16; ks++) {
            unsigned a[2][4];
#pragma unroll
            for (int mt = 0; mt < 2; mt++) {
                unsigned rr[4];
                ldsm_x4(rr, aBase1 + (unsigned)(mt*16*XPITCH*4 + ks*32));
                a[mt][0] = f2tf32(__uint_as_float(rr[0]));
                a[mt][1] = f2tf32(__uint_as_float(rr[1]));
                a[mt][2] = f2tf32(__uint_as_float(rr[2]));
                a[mt][3] = f2tf32(__uint_as_float(rr[3]));
            }
            const float4* bp = (const float4*)g_w1f + (ks*32 + warp*4)*32 + lane;
#pragma unroll
            for (int j4 = 0; j4 < 4; j4++) {
                float4 b = bp[j4*32];
#pragma unroll
                for (int mt = 0; mt < 2; mt++) {
                    mma_tf32(acc[mt][2*j4],   a[mt][0],a[mt][1],a[mt][2],a[mt][3], __float_as_uint(b.x), __float_as_uint(b.y));
                    mma_tf32(acc[mt][2*j4+1], a[mt][0],a[mt][1],a[mt][2],a[mt][3], __float_as_uint(b.z), __float_as_uint(b.w));
                }
            }
        }
#pragma unroll
        for (int mt = 0; mt < 2; mt++) {
#pragma unroll
            for (int t = 0; t < 8; t++) {
                int col = warp*64 + t*8 + 2*tig;
                int r0 = mt*16 + gid, r1 = r0 + 8;
                float h00 = acc[mt][t][0] + b1[col];
                float h01 = acc[mt][t][1] + b1[col+1];
                float h10 = acc[mt][t][2] + b1[col];
                float h11 = acc[mt][t][3] + b1[col+1];
                h00 = 0.5f*h00*(1.f + erff(h00*0.70710678118654752f));
                h01 = 0.5f*h01*(1.f + erff(h01*0.70710678118654752f));
                h10 = 0.5f*h10*(1.f + erff(h10*0.70710678118654752f));
                h11 = 0.5f*h11*(1.f + erff(h11*0.70710678118654752f));
                *(float2*)(&sH[r0*HPITCH + col]) =
                    make_float2(__uint_as_float(f2tf32(h00)), __uint_as_float(f2tf32(h01)));
                *(float2*)(&sH[r1*HPITCH + col]) =
                    make_float2(__uint_as_float(f2tf32(h10)), __uint_as_float(f2tf32(h11)));
            }
        }
    }
    __syncthreads();

    // GEMM2: warp = cols [warp*16, +16) x rows 0..31
    float acc2[2][2][4];
#pragma unroll
    for (int mt = 0; mt < 2; mt++)
#pragma unroll
        for (int nt = 0; nt < 2; nt++)
#pragma unroll
            for (int j = 0; j < 4; j++) acc2[mt][nt][j] = 0.f;
    {
#pragma unroll 4
        for (int ks = 0; ks < 64; ks++) {
            unsigned a[2][4];
            ldsm_x4(a[0], aBase2 + (unsigned)(ks*32));
            ldsm_x4(a[1], aBase2 + (unsigned)(16*HPITCH*4 + ks*32));
            float4 b = ((const float4*)g_w2f)[(ks*8 + warp)*32 + lane];
#pragma unroll
            for (int mt = 0; mt < 2; mt++) {
                mma_tf32(acc2[mt][0], a[mt][0],a[mt][1],a[mt][2],a[mt][3], __float_as_uint(b.x), __float_as_uint(b.y));
                mma_tf32(acc2[mt][1], a[mt][0],a[mt][1],a[mt][2],a[mt][3], __float_as_uint(b.z), __float_as_uint(b.w));
            }
        }
    }
    __syncthreads();   // reads of sH done; reuse as out tile

#pragma unroll
    for (int mt = 0; mt < 2; mt++) {
#pragma unroll
        for (int nt = 0; nt < 2; nt++) {
            int col = warp*16 + nt*8 + 2*tig;
            int r0 = mt*16 + gid, r1 = r0 + 8;
            float2 lo, hi;
            lo.x = acc2[mt][nt][0] + b2[col]   + sX[r0*XPITCH + col];
            lo.y = acc2[mt][nt][1] + b2[col+1] + sX[r0*XPITCH + col + 1];
            hi.x = acc2[mt][nt][2] + b2[col]   + sX[r1*XPITCH + col];
            hi.y = acc2[mt][nt][3] + b2[col+1] + sX[r1*XPITCH + col + 1];
            *(float2*)(&sH[r0*XPITCH + col]) = lo;
            *(float2*)(&sH[r1*XPITCH + col]) = hi;
        }
    }
    __syncthreads();

#pragma unroll
    for (int rr = 0; rr < 4; rr++) {
        int r = warp*4 + rr;
        float v0 = sH[r*XPITCH+lane],    v1 = sH[r*XPITCH+lane+32];
        float v2 = sH[r*XPITCH+lane+64], v3 = sH[r*XPITCH+lane+96];
        float sum = v0+v1+v2+v3;
        float sq  = v0*v0+v1*v1+v2*v2+v3*v3;
        for (int o = 16; o; o >>= 1) {
            sum += __shfl_xor_sync(~0u, sum, o);
            sq  += __shfl_xor_sync(~0u, sq,  o);
        }
        float mu = sum*(1.f/128.f);
        float rs = rsqrtf(sq*(1.f/128.f) - mu*mu + 1e-5f);
        long go = ((long)(row0+r))*C;
        outp[go+lane]    = (v0-mu)*rs*lg2[lane]    + lb2[lane];
        outp[go+lane+32] = (v1-mu)*rs*lg2[lane+32] + lb2[lane+32];
        outp[go+lane+64] = (v2-mu)*rs*lg2[lane+64] + lb2[lane+64];
        outp[go+lane+96] = (v3-mu)*rs*lg2[lane+96] + lb2[lane+96];
    }
}

// ---------------------------------------------------------------------------
extern "C" void kernel_launch(void* const* d_in, const int* in_sizes, int n_in,
                              void* d_out, int out_size)
{
    const float* feat_l = (const float*)d_in[0];
    const float* feat_r = (const float*)d_in[1];
    const float* prev_l = (const float*)d_in[2];
    const float* prev_r = (const float*)d_in[3];
    const float* kqv_w  = (const float*)d_in[4];
    const float* ff_w1  = (const float*)d_in[5];
    const float* ff_b1  = (const float*)d_in[6];
    const float* ff_w2  = (const float*)d_in[7];
    const float* ff_b2  = (const float*)d_in[8];
    const float* ln1_g  = (const float*)d_in[9];
    const float* ln1_b  = (const float*)d_in[10];
    const float* ln2_g  = (const float*)d_in[11];
    const float* ln2_b  = (const float*)d_in[12];
    float* out = (float*)d_out;

    const int FFN_SMEM = (32*XPITCH + 32*HPITCH) * 4;   // 82944 B
    cudaFuncSetAttribute(ffn_kernel, cudaFuncAttributeMaxDynamicSharedMemorySize, FFN_SMEM);
    cudaFuncSetAttribute(attn_kernel, cudaFuncAttributeMaxDynamicSharedMemorySize, ATTN_SMEM);

    proj_kernel<<<dim3(NTOK/32, 2), 256>>>(feat_l, feat_r, kqv_w, ff_w1, ff_w2);
    attn_kernel<<<dim3(SW/32, NSEQ, 2), 256, ATTN_SMEM>>>(prev_l, prev_r, out);
    ffn_kernel<<<dim3(NTOK/32, 2), 256, FFN_SMEM>>>(
        feat_l, feat_r, ff_b1, ff_b2,
        ln1_g, ln1_b, ln2_g, ln2_b, out);
}

// round 16
// speedup vs baseline: 1.1884x; 1.0237x over previous
#include <cuda_runtime.h>
#include <cuda_bf16.h>
#include <math.h>

#define NSEQ 80
#define SW 256
#define C 128
#define NH 8
#define DH 16
#define FF 512
#define NTOK (NSEQ*SW)          // 20480
#define TOKC (NTOK*C)           // 2621440

#define OUT_L 0
#define OUT_R TOKC
#define RAW_L (2*TOKC)
#define RAW_R (2*TOKC + NSEQ*SW*SW*NH)

// Scratch (device globals: allocation-free)
__device__ float g_k[2][TOKC];
__device__ float g_q[2][TOKC];
__device__ float g_v[2][TOKC];
__device__ float g_w1f[16*32*32*4];   // W1 tf32 frag layout
__device__ float g_w2f[64*8*32*4];    // W2 tf32 frag layout

// ---- mma helpers ----
__device__ __forceinline__ unsigned f2tf32(float x) {
    unsigned r; asm("cvt.rna.tf32.f32 %0, %1;" : "=r"(r) : "f"(x)); return r;
}
__device__ __forceinline__ void mma_tf32(float* c,
    unsigned a0, unsigned a1, unsigned a2, unsigned a3,
    unsigned b0, unsigned b1)
{
    asm("mma.sync.aligned.m16n8k8.row.col.f32.tf32.tf32.f32 "
        "{%0,%1,%2,%3},{%4,%5,%6,%7},{%8,%9},{%0,%1,%2,%3};"
        : "+f"(c[0]), "+f"(c[1]), "+f"(c[2]), "+f"(c[3])
        : "r"(a0), "r"(a1), "r"(a2), "r"(a3), "r"(b0), "r"(b1));
}
__device__ __forceinline__ void mma_bf16(float* c,
    const unsigned* a, unsigned b0, unsigned b1)
{
    asm("mma.sync.aligned.m16n8k16.row.col.f32.bf16.bf16.f32 "
        "{%0,%1,%2,%3},{%4,%5,%6,%7},{%8,%9},{%0,%1,%2,%3};"
        : "+f"(c[0]), "+f"(c[1]), "+f"(c[2]), "+f"(c[3])
        : "r"(a[0]), "r"(a[1]), "r"(a[2]), "r"(a[3]), "r"(b0), "r"(b1));
}
__device__ __forceinline__ void bfsplit(float2 v, unsigned& hi, unsigned& lo) {
    __nv_bfloat162 h = __floats2bfloat162_rn(v.x, v.y);
    float2 hf = __bfloat1622float2(h);
    __nv_bfloat162 l = __floats2bfloat162_rn(v.x - hf.x, v.y - hf.y);
    hi = *reinterpret_cast<unsigned*>(&h);
    lo = *reinterpret_cast<unsigned*>(&l);
}
__device__ __forceinline__ void ldsm_x4(unsigned* r, unsigned saddr) {
    asm volatile("ldmatrix.sync.aligned.m8n8.x4.shared.b16 {%0,%1,%2,%3}, [%4];"
        : "=r"(r[0]), "=r"(r[1]), "=r"(r[2]), "=r"(r[3]) : "r"(saddr));
}

#define EXP_SCALE 0.36067376022224085f   // 0.25 * log2(e)

// ---------------------------------------------------------------------------
// Kernel 1: per-head KQV projection (+ W1/W2 frag prep folded in).
// ---------------------------------------------------------------------------
__global__ __launch_bounds__(256) void proj_kernel(
    const float* __restrict__ feat_l, const float* __restrict__ feat_r,
    const float* __restrict__ kqv_w,
    const float* __restrict__ w1, const float* __restrict__ w2)
{
    __shared__ float sW[16*48];
    __shared__ float sO[8*548];
    int tid = threadIdx.x;
    for (int i = tid; i < 16*48; i += 256) sW[i] = kqv_w[i];

    int side = blockIdx.y;

    if (side == 0 && blockIdx.x < 128) {
        int i = blockIdx.x * 256 + tid;     // 0..32767
        if (i < 16384) {
            int lane = i & 31, tp = (i >> 5) & 31, ks = i >> 10;
            int gid = lane >> 2, tig = lane & 3;
            int k0 = ks*8, n0 = (2*tp)*8, n1 = (2*tp+1)*8;
            float4 o;
            o.x = __uint_as_float(f2tf32(w1[(k0+tig)*FF   + n0+gid]));
            o.y = __uint_as_float(f2tf32(w1[(k0+tig+4)*FF + n0+gid]));
            o.z = __uint_as_float(f2tf32(w1[(k0+tig)*FF   + n1+gid]));
            o.w = __uint_as_float(f2tf32(w1[(k0+tig+4)*FF + n1+gid]));
            ((float4*)g_w1f)[i] = o;
        } else {
            int j = i - 16384;
            int lane = j & 31, tp = (j >> 5) & 7, ks = j >> 8;
            int gid = lane >> 2, tig = lane & 3;
            int k0 = ks*8, n0 = (2*tp)*8, n1 = (2*tp+1)*8;
            float4 o;
            o.x = __uint_as_float(f2tf32(w2[(k0+tig)*C   + n0+gid]));
            o.y = __uint_as_float(f2tf32(w2[(k0+tig+4)*C + n0+gid]));
            o.z = __uint_as_float(f2tf32(w2[(k0+tig)*C   + n1+gid]));
            o.w = __uint_as_float(f2tf32(w2[(k0+tig+4)*C + n1+gid]));
            ((float4*)g_w2f)[j] = o;
        }
    }

    const float* feat = side ? feat_r : feat_l;
    int rl = tid >> 3;
    int h  = tid & 7;
    int row = blockIdx.x * 32 + rl;
    __syncthreads();

    float x[16];
    const float4* xp = (const float4*)(feat + (long)row*C + h*DH);
#pragma unroll
    for (int i = 0; i < 4; i++) {
        float4 t = xp[i];
        x[4*i+0]=t.x; x[4*i+1]=t.y; x[4*i+2]=t.z; x[4*i+3]=t.w;
    }
    float o[48];
#pragma unroll
    for (int j = 0; j < 48; j++) o[j] = 0.f;
#pragma unroll
    for (int i = 0; i < 16; i++) {
        float xi = x[i];
#pragma unroll
        for (int j = 0; j < 48; j++) o[j] = fmaf(xi, sW[i*48+j], o[j]);
    }

    int nn = row >> 8;
    int s0 = (blockIdx.x * 32) & 255;
    float* gdst[3] = { g_k[side], g_q[side], g_v[side] };

#pragma unroll
    for (int a = 0; a < 3; a++) {
        __syncthreads();
#pragma unroll
        for (int d = 0; d < 16; d++) sO[h*548 + rl*17 + d] = o[a*16 + d];
        __syncthreads();
        float* gp = gdst[a] + (((long)(nn*NH))*SW + s0) * DH;
        for (int j = tid; j < 4096; j += 256) {
            int hh = j >> 9, rem = j & 511, ss = rem >> 4, d = rem & 15;
            gp[(long)hh*SW*DH + ss*DH + d] = sO[hh*548 + ss*17 + d];
        }
    }
}

// ---------------------------------------------------------------------------
// Kernel 2: FUSED attention + FFN. One block = 32 tokens (lt, nn, side).
// Phase A (attn): QK bf16-split mma -> raw/exp/z -> AV tf32 mma -> msg in regs.
// Phase B (ffn): msg -> smem, +feat, LN1, GEMM1 gelu, GEMM2, +res, LN2 -> out.
// smem phases alias (sX/sH written only after sP/sK/sV are dead).
// ---------------------------------------------------------------------------
#define PL 268    // sP pitch per l:  l*268 + h*33 + s
#define PK 172    // sK pitch per s:  s*172 + h*20 + d
#define PV 168    // sV pitch per s
#define XPITCH 132
#define HPITCH 516
#define FUSED_SMEM ((32*XPITCH + 32*HPITCH)*4)   // 82944 B (>= attn's 77824)

__global__ __launch_bounds__(256, 2) void fused_kernel(
    const float* __restrict__ prev_l, const float* __restrict__ prev_r,
    const float* __restrict__ feat_l, const float* __restrict__ feat_r,
    const float* __restrict__ b1, const float* __restrict__ b2,
    const float* __restrict__ lg1, const float* __restrict__ lb1,
    const float* __restrict__ lg2, const float* __restrict__ lb2,
    float* __restrict__ d_out)
{
    extern __shared__ float sm[];
    float* sP = sm;                  // attn: 32*268
    float* sK = sm + 32*PL;          // attn: 32*172
    float* sV = sm + 32*PL + 32*PK;  // attn: 32*168
    float* sX = sm;                  // ffn:  32*132 (after attn done)
    float* sH = sm + 32*XPITCH;      // ffn:  32*516

    int tid = threadIdx.x;
    int lane = tid & 31;
    int h = tid >> 5;                // warp = head (attn) / warp id (ffn)
    int gid = lane >> 2, tig = lane & 3;
    int lt = blockIdx.x, nn = blockIdx.y, side = blockIdx.z;
    int l0 = lt * 32;

    const float* prev = side ? prev_r : prev_l;
    float* raw = d_out + (side ? RAW_R : RAW_L);
    const float* qb = g_q[side];
    const float* kb = g_k[side ^ 1];
    const float* vb = g_v[side ^ 1];

    // ================= Phase A: attention =================
    unsigned qhi[2][4], qlo[2][4];
    {
        const float* qbase = qb + (((long)(nn*NH + h))*SW + l0)*DH;
#pragma unroll
        for (int mt = 0; mt < 2; mt++) {
            const float* r0 = qbase + (mt*16 + gid)*DH;
            const float* r1 = r0 + 8*DH;
            bfsplit(*(const float2*)(r0 + 2*tig),     qhi[mt][0], qlo[mt][0]);
            bfsplit(*(const float2*)(r1 + 2*tig),     qhi[mt][1], qlo[mt][1]);
            bfsplit(*(const float2*)(r0 + 2*tig + 8), qhi[mt][2], qlo[mt][2]);
            bfsplit(*(const float2*)(r1 + 2*tig + 8), qhi[mt][3], qlo[mt][3]);
        }
    }

    float z00 = 0.f, z01 = 0.f, z10 = 0.f, z11 = 0.f;
    float acc[2][2][4];
#pragma unroll
    for (int mt = 0; mt < 2; mt++)
#pragma unroll
        for (int nt = 0; nt < 2; nt++)
#pragma unroll
            for (int j = 0; j < 4; j++) acc[mt][nt][j] = 0.f;

    for (int ch = 0; ch < 8; ch++) {
        int s0 = ch * 32;
        __syncthreads();

        // stage prev chunk [32l][32s][8h] -> sP[l][h][s]  (streaming read)
#pragma unroll
        for (int i = 0; i < 8; i++) {
            int f = i*256 + tid;
            int l = f >> 6, rem = f & 63;
            int s = rem >> 1, hb = (rem & 1) * 4;
            float4 pv = __ldcs((const float4*)(prev + (((long)(nn*SW + l0+l))*SW + s0+s)*NH + hb));
            float* dp = sP + l*PL + hb*33 + s;
            dp[0] = pv.x; dp[33] = pv.y; dp[66] = pv.z; dp[99] = pv.w;
        }
        // stage K, V chunks
#pragma unroll
        for (int i = 0; i < 4; i++) {
            int f = i*256 + tid;
            int hh = f >> 7, rem = f & 127;
            int s = rem >> 2, dq = rem & 3;
            long src = (((long)(nn*NH + hh))*SW + s0 + s)*DH + dq*4;
            *(float4*)(sK + s*PK + hh*20 + dq*4) = *(const float4*)(kb + src);
            *(float4*)(sV + s*PV + hh*20 + dq*4) = *(const float4*)(vb + src);
        }
        __syncthreads();

        // QK mma (bf16 split, k16)
        float c[2][4][4];
#pragma unroll
        for (int mt = 0; mt < 2; mt++)
#pragma unroll
            for (int st = 0; st < 4; st++)
#pragma unroll
                for (int j = 0; j < 4; j++) c[mt][st][j] = 0.f;

#pragma unroll
        for (int st = 0; st < 4; st++) {
            const float* kr = sK + (st*8 + gid)*PK + h*20;
            unsigned k0h, k0l, k1h, k1l;
            bfsplit(*(const float2*)(kr + 2*tig),     k0h, k0l);
            bfsplit(*(const float2*)(kr + 2*tig + 8), k1h, k1l);
#pragma unroll
            for (int mt = 0; mt < 2; mt++) {
                mma_bf16(c[mt][st], qhi[mt], k0h, k1h);
                mma_bf16(c[mt][st], qhi[mt], k0l, k1l);
                mma_bf16(c[mt][st], qlo[mt], k0h, k1h);
            }
        }

        // prev add, raw (in sP), exp, z
#pragma unroll
        for (int mt = 0; mt < 2; mt++) {
#pragma unroll
            for (int st = 0; st < 4; st++) {
                float* pp = sP + (mt*16 + gid)*PL + h*33 + st*8 + 2*tig;
                float r0 = c[mt][st][0] + pp[0];
                float r1 = c[mt][st][1] + pp[1];
                float r2 = c[mt][st][2] + pp[8*PL];
                float r3 = c[mt][st][3] + pp[8*PL + 1];
                pp[0] = r0; pp[1] = r1; pp[8*PL] = r2; pp[8*PL + 1] = r3;
                float e0 = exp2f(EXP_SCALE*r0), e1 = exp2f(EXP_SCALE*r1);
                float e2 = exp2f(EXP_SCALE*r2), e3 = exp2f(EXP_SCALE*r3);
                if (mt == 0) { z00 += e0 + e1; z01 += e2 + e3; }
                else         { z10 += e0 + e1; z11 += e2 + e3; }
                c[mt][st][0] = e0; c[mt][st][1] = e1; c[mt][st][2] = e2; c[mt][st][3] = e3;
            }
        }

        // AV mma (tf32 k8)
        int srcA = (lane & 28) | (tig >> 1);
        int srcB = srcA + 2;
        bool odd = (tig & 1);
#pragma unroll
        for (int st = 0; st < 4; st++) {
            unsigned a[2][4];
#pragma unroll
            for (int mt = 0; mt < 2; mt++) {
                float e0 = c[mt][st][0], e1 = c[mt][st][1];
                float e2 = c[mt][st][2], e3 = c[mt][st][3];
                float g00 = __shfl_sync(0xffffffffu, e0, srcA);
                float g01 = __shfl_sync(0xffffffffu, e1, srcA);
                float g20 = __shfl_sync(0xffffffffu, e2, srcA);
                float g21 = __shfl_sync(0xffffffffu, e3, srcA);
                float h00 = __shfl_sync(0xffffffffu, e0, srcB);
                float h01 = __shfl_sync(0xffffffffu, e1, srcB);
                float h20 = __shfl_sync(0xffffffffu, e2, srcB);
                float h21 = __shfl_sync(0xffffffffu, e3, srcB);
                a[mt][0] = f2tf32(odd ? g01 : g00);
                a[mt][1] = f2tf32(odd ? g21 : g20);
                a[mt][2] = f2tf32(odd ? h01 : h00);
                a[mt][3] = f2tf32(odd ? h21 : h20);
            }
            const float* vr0 = sV + (st*8 + tig)*PV + h*20;
            const float* vr1 = sV + (st*8 + tig + 4)*PV + h*20;
#pragma unroll
            for (int nt = 0; nt < 2; nt++) {
                unsigned vb0 = f2tf32(vr0[nt*8 + gid]);
                unsigned vb1 = f2tf32(vr1[nt*8 + gid]);
                mma_tf32(acc[0][nt], a[0][0], a[0][1], a[0][2], a[0][3], vb0, vb1);
                mma_tf32(acc[1][nt], a[1][0], a[1][1], a[1][2], a[1][3], vb0, vb1);
            }
        }

        // raw out: sP -> gmem (coalesced, streaming write)
        __syncthreads();
#pragma unroll
        for (int i = 0; i < 8; i++) {
            int f = i*256 + tid;
            int l = f >> 6, rem = f & 63;
            int s = rem >> 1, hb = (rem & 1) * 4;
            float* dp = sP + l*PL + hb*33 + s;
            float4 rv = make_float4(dp[0], dp[33], dp[66], dp[99]);
            __stcs((float4*)(raw + (((long)(nn*SW + l0+l))*SW + s0+s)*NH + hb), rv);
        }
    }

    // z quad-reduce
    z00 += __shfl_xor_sync(0xffffffffu, z00, 1); z00 += __shfl_xor_sync(0xffffffffu, z00, 2);
    z01 += __shfl_xor_sync(0xffffffffu, z01, 1); z01 += __shfl_xor_sync(0xffffffffu, z01, 2);
    z10 += __shfl_xor_sync(0xffffffffu, z10, 1); z10 += __shfl_xor_sync(0xffffffffu, z10, 2);
    z11 += __shfl_xor_sync(0xffffffffu, z11, 1); z11 += __shfl_xor_sync(0xffffffffu, z11, 2);
    float iz[2][2] = { {1.f/z00, 1.f/z01}, {1.f/z10, 1.f/z11} };

    __syncthreads();   // all raw writeback reads of sP done; sX may overwrite

    // msg -> sX (local rows 0..31, cols = h*16 + nt*8 + 2tig)
#pragma unroll
    for (int mt = 0; mt < 2; mt++) {
#pragma unroll
        for (int nt = 0; nt < 2; nt++) {
            int col = h*DH + nt*8 + 2*tig;
            int r0 = mt*16 + gid, r1 = r0 + 8;
            *(float2*)(&sX[r0*XPITCH + col]) =
                make_float2(acc[mt][nt][0]*iz[mt][0], acc[mt][nt][1]*iz[mt][0]);
            *(float2*)(&sX[r1*XPITCH + col]) =
                make_float2(acc[mt][nt][2]*iz[mt][1], acc[mt][nt][3]*iz[mt][1]);
        }
    }
    __syncthreads();

    // ================= Phase B: FFN =================
    const float* feat = side ? feat_r : feat_l;
    float* outp = d_out + (side ? OUT_R : OUT_L);
    int row0 = nn*SW + l0;

    // feat + msg -> sX
    for (int j = tid; j < 1024; j += 256) {
        int r = j >> 5, c4 = j & 31;
        long gi = ((long)(row0+r))*C + c4*4;
        float4 a = *(const float4*)(feat + gi);
        float4 b = *(float4*)(&sX[r*XPITCH + c4*4]);
        a.x += b.x; a.y += b.y; a.z += b.z; a.w += b.w;
        *(float4*)(&sX[r*XPITCH + c4*4]) = a;
    }
    __syncthreads();

    // LN1 in place
#pragma unroll
    for (int rr = 0; rr < 4; rr++) {
        int r = h*4 + rr;
        float v0 = sX[r*XPITCH+lane],    v1 = sX[r*XPITCH+lane+32];
        float v2 = sX[r*XPITCH+lane+64], v3 = sX[r*XPITCH+lane+96];
        float sum = v0+v1+v2+v3;
        float sq  = v0*v0+v1*v1+v2*v2+v3*v3;
        for (int o = 16; o; o >>= 1) {
            sum += __shfl_xor_sync(~0u, sum, o);
            sq  += __shfl_xor_sync(~0u, sq,  o);
        }
        float mu = sum*(1.f/128.f);
        float rs = rsqrtf(sq*(1.f/128.f) - mu*mu + 1e-5f);
        sX[r*XPITCH+lane]    = (v0-mu)*rs*lg1[lane]    + lb1[lane];
        sX[r*XPITCH+lane+32] = (v1-mu)*rs*lg1[lane+32] + lb1[lane+32];
        sX[r*XPITCH+lane+64] = (v2-mu)*rs*lg1[lane+64] + lb1[lane+64];
        sX[r*XPITCH+lane+96] = (v3-mu)*rs*lg1[lane+96] + lb1[lane+96];
    }
    __syncthreads();

    unsigned sXs = (unsigned)__cvta_generic_to_shared(sX);
    unsigned sHs = (unsigned)__cvta_generic_to_shared(sH);
    int row_off = ((lane >> 3) & 1)*8 + (lane & 7);
    int khB = (lane >> 4) * 16;
    unsigned aBase1 = sXs + (unsigned)(row_off*XPITCH*4 + khB);
    unsigned aBase2 = sHs + (unsigned)(row_off*HPITCH*4 + khB);

    // GEMM1: warp = cols [h*64, +64) x rows 0..31
    {
        float ac1[2][8][4];
#pragma unroll
        for (int mt = 0; mt < 2; mt++)
#pragma unroll
            for (int t = 0; t < 8; t++)
#pragma unroll
                for (int j = 0; j < 4; j++) ac1[mt][t][j] = 0.f;

#pragma unroll 2
        for (int ks = 0; ks < 16; ks++) {
            unsigned a[2][4];
#pragma unroll
            for (int mt = 0; mt < 2; mt++) {
                unsigned rr[4];
                ldsm_x4(rr, aBase1 + (unsigned)(mt*16*XPITCH*4 + ks*32));
                a[mt][0] = f2tf32(__uint_as_float(rr[0]));
                a[mt][1] = f2tf32(__uint_as_float(rr[1]));
                a[mt][2] = f2tf32(__uint_as_float(rr[2]));
                a[mt][3] = f2tf32(__uint_as_float(rr[3]));
            }
            const float4* bp = (const float4*)g_w1f + (ks*32 + h*4)*32 + lane;
#pragma unroll
            for (int j4 = 0; j4 < 4; j4++) {
                float4 b = bp[j4*32];
#pragma unroll
                for (int mt = 0; mt < 2; mt++) {
                    mma_tf32(ac1[mt][2*j4],   a[mt][0],a[mt][1],a[mt][2],a[mt][3], __float_as_uint(b.x), __float_as_uint(b.y));
                    mma_tf32(ac1[mt][2*j4+1], a[mt][0],a[mt][1],a[mt][2],a[mt][3], __float_as_uint(b.z), __float_as_uint(b.w));
                }
            }
        }
#pragma unroll
        for (int mt = 0; mt < 2; mt++) {
#pragma unroll
            for (int t = 0; t < 8; t++) {
                int col = h*64 + t*8 + 2*tig;
                int r0 = mt*16 + gid, r1 = r0 + 8;
                float h00 = ac1[mt][t][0] + b1[col];
                float h01 = ac1[mt][t][1] + b1[col+1];
                float h10 = ac1[mt][t][2] + b1[col];
                float h11 = ac1[mt][t][3] + b1[col+1];
                h00 = 0.5f*h00*(1.f + erff(h00*0.70710678118654752f));
                h01 = 0.5f*h01*(1.f + erff(h01*0.70710678118654752f));
                h10 = 0.5f*h10*(1.f + erff(h10*0.70710678118654752f));
                h11 = 0.5f*h11*(1.f + erff(h11*0.70710678118654752f));
                *(float2*)(&sH[r0*HPITCH + col]) =
                    make_float2(__uint_as_float(f2tf32(h00)), __uint_as_float(f2tf32(h01)));
                *(float2*)(&sH[r1*HPITCH + col]) =
                    make_float2(__uint_as_float(f2tf32(h10)), __uint_as_float(f2tf32(h11)));
            }
        }
    }
    __syncthreads();

    // GEMM2: warp = cols [h*16, +16) x rows 0..31
    float ac2[2][2][4];
#pragma unroll
    for (int mt = 0; mt < 2; mt++)
#pragma unroll
        for (int nt = 0; nt < 2; nt++)
#pragma unroll
            for (int j = 0; j < 4; j++) ac2[mt][nt][j] = 0.f;
    {
#pragma unroll 4
        for (int ks = 0; ks < 64; ks++) {
            unsigned a[2][4];
            ldsm_x4(a[0], aBase2 + (unsigned)(ks*32));
            ldsm_x4(a[1], aBase2 + (unsigned)(16*HPITCH*4 + ks*32));
            float4 b = ((const float4*)g_w2f)[(ks*8 + h)*32 + lane];
#pragma unroll
            for (int mt = 0; mt < 2; mt++) {
                mma_tf32(ac2[mt][0], a[mt][0],a[mt][1],a[mt][2],a[mt][3], __float_as_uint(b.x), __float_as_uint(b.y));
                mma_tf32(ac2[mt][1], a[mt][0],a[mt][1],a[mt][2],a[mt][3], __float_as_uint(b.z), __float_as_uint(b.w));
            }
        }
    }
    __syncthreads();   // reads of sH done; reuse as out tile

#pragma unroll
    for (int mt = 0; mt < 2; mt++) {
#pragma unroll
        for (int nt = 0; nt < 2; nt++) {
            int col = h*16 + nt*8 + 2*tig;
            int r0 = mt*16 + gid, r1 = r0 + 8;
            float2 lo, hi;
            lo.x = ac2[mt][nt][0] + b2[col]   + sX[r0*XPITCH + col];
            lo.y = ac2[mt][nt][1] + b2[col+1] + sX[r0*XPITCH + col + 1];
            hi.x = ac2[mt][nt][2] + b2[col]   + sX[r1*XPITCH + col];
            hi.y = ac2[mt][nt][3] + b2[col+1] + sX[r1*XPITCH + col + 1];
            *(float2*)(&sH[r0*XPITCH + col]) = lo;
            *(float2*)(&sH[r1*XPITCH + col]) = hi;
        }
    }
    __syncthreads();

    // LN2 + write out
#pragma unroll
    for (int rr = 0; rr < 4; rr++) {
        int r = h*4 + rr;
        float v0 = sH[r*XPITCH+lane],    v1 = sH[r*XPITCH+lane+32];
        float v2 = sH[r*XPITCH+lane+64], v3 = sH[r*XPITCH+lane+96];
        float sum = v0+v1+v2+v3;
        float sq  = v0*v0+v1*v1+v2*v2+v3*v3;
        for (int o = 16; o; o >>= 1) {
            sum += __shfl_xor_sync(~0u, sum, o);
            sq  += __shfl_xor_sync(~0u, sq,  o);
        }
        float mu = sum*(1.f/128.f);
        float rs = rsqrtf(sq*(1.f/128.f) - mu*mu + 1e-5f);
        long go = ((long)(row0+r))*C;
        outp[go+lane]    = (v0-mu)*rs*lg2[lane]    + lb2[lane];
        outp[go+lane+32] = (v1-mu)*rs*lg2[lane+32] + lb2[lane+32];
        outp[go+lane+64] = (v2-mu)*rs*lg2[lane+64] + lb2[lane+64];
        outp[go+lane+96] = (v3-mu)*rs*lg2[lane+96] + lb2[lane+96];
    }
}

// ---------------------------------------------------------------------------
extern "C" void kernel_launch(void* const* d_in, const int* in_sizes, int n_in,
                              void* d_out, int out_size)
{
    const float* feat_l = (const float*)d_in[0];
    const float* feat_r = (const float*)d_in[1];
    const float* prev_l = (const float*)d_in[2];
    const float* prev_r = (const float*)d_in[3];
    const float* kqv_w  = (const float*)d_in[4];
    const float* ff_w1  = (const float*)d_in[5];
    const float* ff_b1  = (const float*)d_in[6];
    const float* ff_w2  = (const float*)d_in[7];
    const float* ff_b2  = (const float*)d_in[8];
    const float* ln1_g  = (const float*)d_in[9];
    const float* ln1_b  = (const float*)d_in[10];
    const float* ln2_g  = (const float*)d_in[11];
    const float* ln2_b  = (const float*)d_in[12];
    float* out = (float*)d_out;

    cudaFuncSetAttribute(fused_kernel, cudaFuncAttributeMaxDynamicSharedMemorySize, FUSED_SMEM);

    proj_kernel<<<dim3(NTOK/32, 2), 256>>>(feat_l, feat_r, kqv_w, ff_w1, ff_w2);
    fused_kernel<<<dim3(SW/32, NSEQ, 2), 256, FUSED_SMEM>>>(
        prev_l, prev_r, feat_l, feat_r, ff_b1, ff_b2,
        ln1_g, ln1_b, ln2_g, ln2_b, out);
}